// round 2
// baseline (speedup 1.0000x reference)
#include <cuda_runtime.h>
#include <math.h>
#include <stdint.h>

#define BB 2
#define SS 2048
#define DD 1024
#define DFFN 2816
#define WIN 512
#define NROW (BB*SS)            // 4096
#define HV 32000
#define OUTV 32000
#define SPACE_TOK 36

// ---------------- scratch (device globals; no allocation allowed) ------------
__device__ float    g_embeds[NROW*DD];
__device__ float    g_h[NROW*DD];
__device__ float    g_xn[NROW*DD];
__device__ float    g_q[NROW*DD];
__device__ float    g_k[NROW*DD];
__device__ float    g_v[NROW*DD];
__device__ float    g_attn[NROW*DD];
__device__ unsigned g_pool[NROW*DD];
__device__ float    g_t1[NROW*DFFN];
__device__ float    g_t3[NROW*DFFN];
__device__ int      g_patch[NROW];
__device__ float    g_freq[DD/2];

// ---------------- hash n-gram embeddings ------------------------------------
__global__ void hash_embed_kernel(const int* __restrict__ ids,
                                  const float* __restrict__ tok_emb,
                                  const float* __restrict__ hash_emb,
                                  float* __restrict__ out,
                                  float* __restrict__ out2) {
    int bs = blockIdx.x;
    int s  = bs & (SS - 1);
    __shared__ const float* rows[4];
    if (threadIdx.x == 0) {
        unsigned g0 = (unsigned)ids[bs];
        unsigned g1 = (s >= 1) ? (unsigned)ids[bs-1] : 0u;
        unsigned g2 = (s >= 2) ? (unsigned)ids[bs-2] : 0u;
        unsigned g3 = (s >= 3) ? (unsigned)ids[bs-3] : 0u;
        rows[0] = tok_emb + (size_t)ids[bs] * DD;
        const unsigned mults[3] = {2654435761u, 805459861u, 2246822519u};
        for (int f = 0; f < 3; f++) {
            unsigned a = mults[f];
            unsigned h = g0;
            h = h*a + g1; h = h*a + g2; h = h*a + g3;
            rows[f+1] = hash_emb + ((size_t)f * HV + (h % HV)) * DD;
        }
    }
    __syncthreads();
    const float* r0 = rows[0]; const float* r1 = rows[1];
    const float* r2 = rows[2]; const float* r3 = rows[3];
    size_t base = (size_t)bs * DD;
    for (int d = threadIdx.x; d < DD; d += 256) {
        float v = r0[d] + r1[d] + r2[d] + r3[d];
        out[base + d]  = v;
        out2[base + d] = v;
    }
}

// ---------------- patch ids (sequential scan; trivial size) ------------------
__global__ void patch_kernel(const int* __restrict__ ids, int* __restrict__ patch) {
    int b = threadIdx.x;
    if (b >= BB) return;
    int pid = -1;
    for (int s = 0; s < SS; s++) {
        bool start = (s == 0) || (ids[b*SS + s - 1] == SPACE_TOK);
        if (start) pid++;
        patch[b*SS + s] = pid;
    }
}

// ---------------- rmsnorm ----------------------------------------------------
__global__ void rmsnorm_kernel(const float* __restrict__ x,
                               const float* __restrict__ w,
                               float* __restrict__ y) {
    int row = blockIdx.x;
    const float* xr = x + (size_t)row * DD;
    float ss = 0.f;
    for (int d = threadIdx.x; d < DD; d += 256) { float v = xr[d]; ss += v*v; }
    __shared__ float red[256];
    red[threadIdx.x] = ss; __syncthreads();
    for (int s = 128; s > 0; s >>= 1) {
        if (threadIdx.x < s) red[threadIdx.x] += red[threadIdx.x + s];
        __syncthreads();
    }
    float scale = rsqrtf(red[0] * (1.0f/DD) + 1e-5f);
    float* yr = y + (size_t)row * DD;
    for (int d = threadIdx.x; d < DD; d += 256) yr[d] = xr[d] * scale * w[d];
}

// ---------------- SGEMM 128x128x8, 256 thr, 8x8 micro-tile -------------------
template <bool ACC>
__global__ __launch_bounds__(256)
void sgemm_kernel(int M, int N, int K,
                  const float* __restrict__ A,
                  const float* __restrict__ Bw,
                  float* __restrict__ C) {
    const int BM = 128, BN = 128, BK = 8, TM = 8, TN = 8;
    __shared__ float As[BK][BM];
    __shared__ float Bs[BK][BN];
    const int tid  = threadIdx.x;
    const int cRow = blockIdx.y, cCol = blockIdx.x;
    const int tRow = tid / (BN/TN);   // 0..15
    const int tCol = tid % (BN/TN);   // 0..15
    const int aRow = tid >> 1;            // 0..127
    const int aCol = (tid & 1) * 4;       // 0 or 4
    const int bRow = tid >> 5;            // 0..7
    const int bCol = (tid & 31) * 4;      // 0..124

    const float* Ablk = A  + (size_t)cRow * BM * K;
    const float* Bblk = Bw + (size_t)cCol * BN;
    float acc[TM][TN];
    #pragma unroll
    for (int i = 0; i < TM; i++)
        #pragma unroll
        for (int j = 0; j < TN; j++) acc[i][j] = 0.f;
    float rM[TM], rN[TN];

    for (int k0 = 0; k0 < K; k0 += BK) {
        float4 a4 = *(const float4*)(Ablk + (size_t)aRow * K + k0 + aCol);
        As[aCol+0][aRow] = a4.x; As[aCol+1][aRow] = a4.y;
        As[aCol+2][aRow] = a4.z; As[aCol+3][aRow] = a4.w;
        float4 b4 = *(const float4*)(Bblk + (size_t)(k0 + bRow) * N + bCol);
        *(float4*)&Bs[bRow][bCol] = b4;
        __syncthreads();
        #pragma unroll
        for (int kk = 0; kk < BK; kk++) {
            #pragma unroll
            for (int i = 0; i < TM; i++) rM[i] = As[kk][tRow*TM + i];
            #pragma unroll
            for (int j = 0; j < TN; j++) rN[j] = Bs[kk][tCol*TN + j];
            #pragma unroll
            for (int i = 0; i < TM; i++)
                #pragma unroll
                for (int j = 0; j < TN; j++) acc[i][j] += rM[i] * rN[j];
        }
        __syncthreads();
    }

    float* Cblk = C + (size_t)cRow * BM * N + (size_t)cCol * BN;
    #pragma unroll
    for (int i = 0; i < TM; i++) {
        int r = tRow * TM + i;
        #pragma unroll
        for (int j = 0; j < TN; j += 4) {
            float* cp = Cblk + (size_t)r * N + tCol*TN + j;
            float4 o;
            o.x = acc[i][j+0]; o.y = acc[i][j+1]; o.z = acc[i][j+2]; o.w = acc[i][j+3];
            if (ACC) {
                float4 c = *(float4*)cp;
                o.x += c.x; o.y += c.y; o.z += c.z; o.w += c.w;
            }
            *(float4*)cp = o;
        }
    }
}

static void gemm(const float* A, const float* Bw, float* C,
                 int M, int N, int K, bool acc) {
    dim3 grid(N / 128, M / 128);
    if (acc) sgemm_kernel<true ><<<grid, 256>>>(M, N, K, A, Bw, C);
    else     sgemm_kernel<false><<<grid, 256>>>(M, N, K, A, Bw, C);
}

// ---------------- RoPE -------------------------------------------------------
__global__ void freq_kernel(float* __restrict__ freq) {
    int h = threadIdx.x;
    if (h < DD/2) {
        // 1 / 10000^(h/512), computed in double then rounded
        freq[h] = (float)exp2(-(double)h * (13.287712379549449 / 512.0));
    }
}

__global__ void rope_kernel(float* __restrict__ x, const float* __restrict__ freq) {
    int bs = blockIdx.x;
    int s  = bs & (SS - 1);
    size_t base = (size_t)bs * DD;
    for (int h = threadIdx.x; h < DD/2; h += 256) {
        float ang = (float)s * freq[h];
        float sn, cs;
        sincosf(ang, &sn, &cs);
        float x1 = x[base + h], x2 = x[base + 512 + h];
        x[base + h]       = x1*cs - x2*sn;
        x[base + 512 + h] = x1*sn + x2*cs;
    }
}

// ---------------- windowed causal attention ----------------------------------
__global__ __launch_bounds__(256)
void attn_kernel(const float* __restrict__ q, const float* __restrict__ k,
                 const float* __restrict__ v, float* __restrict__ o) {
    int i = blockIdx.x, b = blockIdx.y;
    __shared__ float qs[DD];
    __shared__ float sc[WIN];
    __shared__ float red[256];
    const int tid = threadIdx.x, warp = tid >> 5, lane = tid & 31;

    const float* qr = q + ((size_t)b*SS + i) * DD;
    for (int d = tid; d < DD; d += 256) qs[d] = qr[d];
    __syncthreads();

    int j0 = max(0, i - WIN + 1);
    int nk = i - j0 + 1;

    // warp-per-key dot products
    for (int jj = warp; jj < nk; jj += 8) {
        const float* kr = k + ((size_t)b*SS + j0 + jj) * DD;
        float acc = 0.f;
        for (int c = lane; c < DD; c += 32) acc += qs[c] * kr[c];
        #pragma unroll
        for (int off = 16; off; off >>= 1) acc += __shfl_xor_sync(0xffffffffu, acc, off);
        if (lane == 0) sc[jj] = acc * (1.0f / 32.0f);   // 1/sqrt(1024)
    }
    __syncthreads();

    // softmax
    float m = -INFINITY;
    for (int jj = tid; jj < nk; jj += 256) m = fmaxf(m, sc[jj]);
    red[tid] = m; __syncthreads();
    for (int s = 128; s > 0; s >>= 1) {
        if (tid < s) red[tid] = fmaxf(red[tid], red[tid + s]);
        __syncthreads();
    }
    float mx = red[0]; __syncthreads();
    float ssum = 0.f;
    for (int jj = tid; jj < nk; jj += 256) {
        float e = expf(sc[jj] - mx);
        sc[jj] = e; ssum += e;
    }
    red[tid] = ssum; __syncthreads();
    for (int s = 128; s > 0; s >>= 1) {
        if (tid < s) red[tid] += red[tid + s];
        __syncthreads();
    }
    float inv = 1.0f / red[0]; __syncthreads();
    for (int jj = tid; jj < nk; jj += 256) sc[jj] *= inv;
    __syncthreads();

    // PV: four independent accumulation chains, coalesced v reads
    float a0 = 0.f, a1 = 0.f, a2 = 0.f, a3 = 0.f;
    for (int jj = 0; jj < nk; jj++) {
        float p = sc[jj];
        const float* vr = v + ((size_t)b*SS + j0 + jj) * DD;
        a0 += p * vr[tid];
        a1 += p * vr[tid + 256];
        a2 += p * vr[tid + 512];
        a3 += p * vr[tid + 768];
    }
    float* orow = o + ((size_t)b*SS + i) * DD;
    orow[tid]       = a0;
    orow[tid + 256] = a1;
    orow[tid + 512] = a2;
    orow[tid + 768] = a3;
}

// ---------------- SwiGLU elementwise -----------------------------------------
__global__ void swiglu_kernel(float* __restrict__ t1, const float* __restrict__ t3, int n) {
    int i = blockIdx.x * 256 + threadIdx.x;
    if (i < n) {
        float x = t1[i];
        t1[i] = (x / (1.f + expf(-x))) * t3[i];
    }
}

// ---------------- segment max pooling ----------------------------------------
__device__ __forceinline__ unsigned enc_f(float f) {
    unsigned b = __float_as_uint(f);
    return (b & 0x80000000u) ? ~b : (b | 0x80000000u);
}
__device__ __forceinline__ float dec_f(unsigned u) {
    return __uint_as_float((u & 0x80000000u) ? (u & 0x7fffffffu) : ~u);
}

__global__ void pool_max_kernel(const float* __restrict__ x,
                                const int* __restrict__ patch,
                                unsigned* __restrict__ pool) {
    int bs = blockIdx.x;
    int b  = bs >> 11;
    int p  = patch[bs];
    unsigned* dst = pool + ((size_t)b*SS + p) * DD;
    const float* src = x + (size_t)bs * DD;
    for (int d = threadIdx.x; d < DD; d += 256)
        atomicMax(dst + d, enc_f(src[d]));
}

__global__ void gather_add_kernel(const float* __restrict__ embeds,
                                  const unsigned* __restrict__ pool,
                                  const int* __restrict__ patch,
                                  float* __restrict__ hd) {
    int bs = blockIdx.x;
    int b  = bs >> 11;
    int p  = patch[bs];
    const unsigned* src = pool + ((size_t)b*SS + p) * DD;
    size_t base = (size_t)bs * DD;
    for (int d = threadIdx.x; d < DD; d += 256) {
        float g = dec_f(src[d]);
        if (!isfinite(g)) g = 0.f;
        hd[base + d] = embeds[base + d] + g;
    }
}

// ---------------- one transformer layer --------------------------------------
static void run_layer(float* h, float* xn, float* q, float* k, float* v,
                      float* attn, float* t1, float* t3, float* freq,
                      const float* const* W) {
    // W: 0=wq 1=wk 2=wv 3=wo 4=w1 5=w2 6=w3 7=norm_attn 8=norm_ffn
    rmsnorm_kernel<<<NROW, 256>>>(h, W[7], xn);
    gemm(xn, W[0], q, NROW, DD, DD, false);
    gemm(xn, W[1], k, NROW, DD, DD, false);
    gemm(xn, W[2], v, NROW, DD, DD, false);
    rope_kernel<<<NROW, 256>>>(q, freq);
    rope_kernel<<<NROW, 256>>>(k, freq);
    attn_kernel<<<dim3(SS, BB), 256>>>(q, k, v, attn);
    gemm(attn, W[3], h, NROW, DD, DD, true);        // residual add
    rmsnorm_kernel<<<NROW, 256>>>(h, W[8], xn);
    gemm(xn, W[4], t1, NROW, DFFN, DD, false);
    gemm(xn, W[6], t3, NROW, DFFN, DD, false);
    swiglu_kernel<<<(NROW*DFFN + 255)/256, 256>>>(t1, t3, NROW*DFFN);
    gemm(t1, W[5], h, NROW, DD, DFFN, true);        // residual add
}

// ---------------- entry ------------------------------------------------------
extern "C" void kernel_launch(void* const* d_in, const int* in_sizes, int n_in,
                              void* d_out, int out_size) {
    const int*   ids      = (const int*)d_in[0];
    const float* tok_emb  = (const float*)d_in[1];
    const float* hash_emb = (const float*)d_in[2];
    const float* W[21];
    for (int i = 0; i < 21; i++) W[i] = (const float*)d_in[3 + i];
    // enc: W[0..9] = wq wk wv wo w1 w2 w3 n_attn n_ffn n_out
    // dec: W[10..19], out_proj = W[20]
    float* out = (float*)d_out;

    float *embeds, *h, *xn, *q, *k, *v, *attn, *t1, *t3, *freq;
    unsigned* pool; int* patch;
    cudaGetSymbolAddress((void**)&embeds, g_embeds);
    cudaGetSymbolAddress((void**)&h,      g_h);
    cudaGetSymbolAddress((void**)&xn,     g_xn);
    cudaGetSymbolAddress((void**)&q,      g_q);
    cudaGetSymbolAddress((void**)&k,      g_k);
    cudaGetSymbolAddress((void**)&v,      g_v);
    cudaGetSymbolAddress((void**)&attn,   g_attn);
    cudaGetSymbolAddress((void**)&t1,     g_t1);
    cudaGetSymbolAddress((void**)&t3,     g_t3);
    cudaGetSymbolAddress((void**)&pool,   g_pool);
    cudaGetSymbolAddress((void**)&patch,  g_patch);
    cudaGetSymbolAddress((void**)&freq,   g_freq);

    freq_kernel<<<1, 512>>>(freq);
    hash_embed_kernel<<<NROW, 256>>>(ids, tok_emb, hash_emb, embeds, h);
    patch_kernel<<<1, 32>>>(ids, patch);

    // encoder layer
    run_layer(h, xn, q, k, v, attn, t1, t3, freq, W + 0);

    // encoder out-norm -> pooling -> decoder input
    rmsnorm_kernel<<<NROW, 256>>>(h, W[9], xn);
    cudaMemsetAsync(pool, 0, (size_t)NROW * DD * sizeof(unsigned));
    pool_max_kernel<<<NROW, 256>>>(xn, patch, pool);
    gather_add_kernel<<<NROW, 256>>>(embeds, pool, patch, h);

    // decoder layer
    run_layer(h, xn, q, k, v, attn, t1, t3, freq, W + 10);

    // final norm + output projection
    rmsnorm_kernel<<<NROW, 256>>>(h, W[19], xn);
    gemm(xn, W[20], out, NROW, OUTV, DD, false);
}

// round 5
// speedup vs baseline: 2.0325x; 2.0325x over previous
#include <cuda_runtime.h>
#include <cuda_bf16.h>
#include <math.h>
#include <stdint.h>

#define BB 2
#define SS 2048
#define DD 1024
#define DFFN 2816
#define WIN 512
#define NROW (BB*SS)            // 4096
#define HV 32000
#define OUTV 32000
#define SPACE_TOK 36

typedef unsigned short u16;

// ---------------- scratch (device globals; no allocation allowed) ------------
__device__ float    g_embeds[NROW*DD];
__device__ float    g_h[NROW*DD];
__device__ float    g_xn[NROW*DD];
__device__ float    g_q[NROW*DD];
__device__ float    g_k[NROW*DD];
__device__ float    g_v[NROW*DD];
__device__ unsigned g_pool[NROW*DD];
__device__ float    g_t1[NROW*DFFN];
__device__ float    g_t3[NROW*DFFN];
__device__ int      g_patch[NROW];
__device__ float    g_freq[DD/2];
// bf16 hi/lo split weights (pre-transposed to [N,K]) and activations
__device__ u16 g_wh[58458112];
__device__ u16 g_wl[58458112];
__device__ u16 g_ah[(size_t)NROW*DFFN];
__device__ u16 g_al[(size_t)NROW*DFFN];

static __device__ __forceinline__ uint32_t smem_u32(const void* p){
    uint32_t a;
    asm("{ .reg .u64 t; cvta.to.shared.u64 t, %1; cvt.u32.u64 %0, t; }"
        : "=r"(a) : "l"(p));
    return a;
}

// ================= mma.sync bf16x3 GEMM ======================================
// C[M,N] (+)= A[M,K] * W^T  with W pre-transposed to [N,K].
// Split precision: A = Ah + Al, B = Bh + Bl (bf16 each);
// C ~= Ah*Bh + Al*Bh + Ah*Bl  (fp32 accumulate) -> ~2^-18 relative error.
//
// smem tiles padded to 48B rows: 16 halves data + 8 pad. (3r+c) mod 8 is a
// permutation over 8 rows => ldmatrix conflict-free.
#define TILE_B 6144          // 128 rows * 48 bytes
#define STAGE_B 24576        // Ah,Al,Bh,Bl tiles
#define GEMM_SMEM (2*STAGE_B)

static __device__ __forceinline__ void ldsm_x4(uint32_t* r, uint32_t addr){
    asm volatile("ldmatrix.sync.aligned.m8n8.x4.shared.b16 {%0,%1,%2,%3}, [%4];"
                 : "=r"(r[0]), "=r"(r[1]), "=r"(r[2]), "=r"(r[3]) : "r"(addr));
}
static __device__ __forceinline__ void ldsm_x2(uint32_t* r, uint32_t addr){
    asm volatile("ldmatrix.sync.aligned.m8n8.x2.shared.b16 {%0,%1}, [%2];"
                 : "=r"(r[0]), "=r"(r[1]) : "r"(addr));
}
static __device__ __forceinline__ void mma16816(float* d, const uint32_t* a, const uint32_t* b){
    asm volatile(
        "mma.sync.aligned.m16n8k16.row.col.f32.bf16.bf16.f32 "
        "{%0,%1,%2,%3}, {%4,%5,%6,%7}, {%8,%9}, {%0,%1,%2,%3};"
        : "+f"(d[0]), "+f"(d[1]), "+f"(d[2]), "+f"(d[3])
        : "r"(a[0]), "r"(a[1]), "r"(a[2]), "r"(a[3]), "r"(b[0]), "r"(b[1]));
}

template<bool ACC>
__global__ void __launch_bounds__(256)
mma_gemm_kernel(int M, int N, int K,
                const u16* __restrict__ Ah, const u16* __restrict__ Al,
                const u16* __restrict__ Bh, const u16* __restrict__ Bl,
                float* __restrict__ C)
{
    extern __shared__ char smem[];
    const uint32_t sb = smem_u32(smem);
    const int tid = threadIdx.x, lane = tid & 31, warp = tid >> 5;
    const int m0 = blockIdx.y * 128, n0 = blockIdx.x * 128;
    const int wm = (warp >> 2) * 64;     // warp M offset: 0/64
    const int wn = (warp & 3) * 32;      // warp N offset: 0/32/64/96

    const u16* srcp[4] = { Ah + (size_t)m0 * K, Al + (size_t)m0 * K,
                           Bh + (size_t)n0 * K, Bl + (size_t)n0 * K };
    // this thread's 4 cp.async chunks: tile, row, 16B-chunk
    const int c_tile[4] = { (tid + 0) >> 8, (tid + 256) >> 8,
                            (tid + 512) >> 8, (tid + 768) >> 8 };
    int c_row[4], c_ch[4];
    #pragma unroll
    for (int j = 0; j < 4; j++){
        int idx = (tid + j*256) & 255;
        c_row[j] = idx >> 1; c_ch[j] = idx & 1;
    }

    float acc[4][4][4];
    #pragma unroll
    for (int a = 0; a < 4; a++)
        #pragma unroll
        for (int b = 0; b < 4; b++)
            #pragma unroll
            for (int c = 0; c < 4; c++) acc[a][b][c] = 0.f;

    const int nstage = K >> 4;

    // prologue: stage 0
    {
        uint32_t sbase = sb;
        #pragma unroll
        for (int j = 0; j < 4; j++){
            uint32_t dst = sbase + c_tile[j]*TILE_B + c_row[j]*48 + c_ch[j]*16;
            const u16* src = srcp[c_tile[j]] + (size_t)c_row[j]*K + c_ch[j]*8;
            asm volatile("cp.async.cg.shared.global [%0], [%1], 16;" :: "r"(dst), "l"(src));
        }
        asm volatile("cp.async.commit_group;");
    }

    const int arow = lane & 15, acolb = (lane >> 4) * 16;
    const int l2 = lane & 15;
    const int brow = l2 & 7, bcolb = ((l2 >> 3) & 1) * 16;

    for (int s = 0; s < nstage; s++){
        if (s + 1 < nstage){
            uint32_t sbase = sb + ((s + 1) & 1) * STAGE_B;
            int k0 = (s + 1) << 4;
            #pragma unroll
            for (int j = 0; j < 4; j++){
                uint32_t dst = sbase + c_tile[j]*TILE_B + c_row[j]*48 + c_ch[j]*16;
                const u16* src = srcp[c_tile[j]] + (size_t)c_row[j]*K + k0 + c_ch[j]*8;
                asm volatile("cp.async.cg.shared.global [%0], [%1], 16;" :: "r"(dst), "l"(src));
            }
        }
        asm volatile("cp.async.commit_group;");
        asm volatile("cp.async.wait_group 1;");
        __syncthreads();

        uint32_t base = sb + (s & 1) * STAGE_B;
        uint32_t aH[4][4], aL[4][4], bH[4][2], bL[4][2];
        #pragma unroll
        for (int mi = 0; mi < 4; mi++){
            uint32_t ad = base + (wm + mi*16 + arow)*48 + acolb;
            ldsm_x4(aH[mi], ad);
            ldsm_x4(aL[mi], ad + TILE_B);
        }
        #pragma unroll
        for (int ni = 0; ni < 4; ni++){
            uint32_t bd = base + 2*TILE_B + (wn + ni*8 + brow)*48 + bcolb;
            ldsm_x2(bH[ni], bd);
            ldsm_x2(bL[ni], bd + TILE_B);
        }
        #pragma unroll
        for (int mi = 0; mi < 4; mi++)
            #pragma unroll
            for (int ni = 0; ni < 4; ni++){
                mma16816(acc[mi][ni], aH[mi], bH[ni]);
                mma16816(acc[mi][ni], aL[mi], bH[ni]);
                mma16816(acc[mi][ni], aH[mi], bL[ni]);
            }
        __syncthreads();
    }

    // epilogue: fragment -> global (optional residual add)
    #pragma unroll
    for (int mi = 0; mi < 4; mi++){
        int r0 = m0 + wm + mi*16 + (lane >> 2);
        #pragma unroll
        for (int ni = 0; ni < 4; ni++){
            int c0 = n0 + wn + ni*8 + (lane & 3)*2;
            float* p0 = C + (size_t)r0 * N + c0;
            float* p1 = p0 + (size_t)8 * N;
            float2 v0 = make_float2(acc[mi][ni][0], acc[mi][ni][1]);
            float2 v1 = make_float2(acc[mi][ni][2], acc[mi][ni][3]);
            if (ACC){
                float2 o0 = *(float2*)p0, o1 = *(float2*)p1;
                v0.x += o0.x; v0.y += o0.y; v1.x += o1.x; v1.y += o1.y;
            }
            *(float2*)p0 = v0;
            *(float2*)p1 = v1;
        }
    }
}

// ---- weight transpose + hi/lo bf16 split: W[K,N] -> Th/Tl[N,K] --------------
__global__ void wsplit_kernel(const float* __restrict__ W,
                              u16* __restrict__ Th,
                              u16* __restrict__ Tl,
                              int K, int N){
    __shared__ float t[32][33];
    int k0 = blockIdx.y * 32, n0 = blockIdx.x * 32;
    int tx = threadIdx.x, ty = threadIdx.y;
    #pragma unroll
    for (int j = 0; j < 32; j += 8)
        t[ty + j][tx] = W[(size_t)(k0 + ty + j) * N + n0 + tx];
    __syncthreads();
    #pragma unroll
    for (int j = 0; j < 32; j += 8){
        float v = t[tx][ty + j];
        __nv_bfloat16 h = __float2bfloat16(v);
        float lo = v - __bfloat162float(h);
        size_t o = (size_t)(n0 + ty + j) * K + k0 + tx;
        Th[o] = __bfloat16_as_ushort(h);
        Tl[o] = __bfloat16_as_ushort(__float2bfloat16(lo));
    }
}

static __device__ __forceinline__ void split2(float v, u16& h, u16& l){
    __nv_bfloat16 hb = __float2bfloat16(v);
    h = __bfloat16_as_ushort(hb);
    l = __bfloat16_as_ushort(__float2bfloat16(v - __bfloat162float(hb)));
}

// ---------------- hash n-gram embeddings ------------------------------------
__global__ void hash_embed_kernel(const int* __restrict__ ids,
                                  const float* __restrict__ tok_emb,
                                  const float* __restrict__ hash_emb,
                                  float* __restrict__ out,
                                  float* __restrict__ out2) {
    int bs = blockIdx.x;
    int s  = bs & (SS - 1);
    __shared__ const float* rows[4];
    if (threadIdx.x == 0) {
        unsigned g0 = (unsigned)ids[bs];
        unsigned g1 = (s >= 1) ? (unsigned)ids[bs-1] : 0u;
        unsigned g2 = (s >= 2) ? (unsigned)ids[bs-2] : 0u;
        unsigned g3 = (s >= 3) ? (unsigned)ids[bs-3] : 0u;
        rows[0] = tok_emb + (size_t)ids[bs] * DD;
        const unsigned mults[3] = {2654435761u, 805459861u, 2246822519u};
        for (int f = 0; f < 3; f++) {
            unsigned a = mults[f];
            unsigned h = g0;
            h = h*a + g1; h = h*a + g2; h = h*a + g3;
            rows[f+1] = hash_emb + ((size_t)f * HV + (h % HV)) * DD;
        }
    }
    __syncthreads();
    const float* r0 = rows[0]; const float* r1 = rows[1];
    const float* r2 = rows[2]; const float* r3 = rows[3];
    size_t base = (size_t)bs * DD;
    for (int d = threadIdx.x; d < DD; d += 256) {
        float v = r0[d] + r1[d] + r2[d] + r3[d];
        out[base + d]  = v;
        out2[base + d] = v;
    }
}

// ---------------- patch ids --------------------------------------------------
__global__ void patch_kernel(const int* __restrict__ ids, int* __restrict__ patch) {
    int b = threadIdx.x;
    if (b >= BB) return;
    int pid = -1;
    for (int s = 0; s < SS; s++) {
        bool start = (s == 0) || (ids[b*SS + s - 1] == SPACE_TOK);
        if (start) pid++;
        patch[b*SS + s] = pid;
    }
}

// ---------------- rmsnorm (fp32 out, for pooling path) ----------------------
__global__ void rmsnorm_kernel(const float* __restrict__ x,
                               const float* __restrict__ w,
                               float* __restrict__ y) {
    int row = blockIdx.x;
    const float* xr = x + (size_t)row * DD;
    float ss = 0.f;
    for (int d = threadIdx.x; d < DD; d += 256) { float v = xr[d]; ss += v*v; }
    __shared__ float red[256];
    red[threadIdx.x] = ss; __syncthreads();
    for (int s = 128; s > 0; s >>= 1) {
        if (threadIdx.x < s) red[threadIdx.x] += red[threadIdx.x + s];
        __syncthreads();
    }
    float scale = rsqrtf(red[0] * (1.0f/DD) + 1e-5f);
    float* yr = y + (size_t)row * DD;
    for (int d = threadIdx.x; d < DD; d += 256) yr[d] = xr[d] * scale * w[d];
}

// ---------------- rmsnorm fused with bf16 hi/lo split ------------------------
__global__ void rmsnorm_split_kernel(const float* __restrict__ x,
                                     const float* __restrict__ w,
                                     u16* __restrict__ hh,
                                     u16* __restrict__ ll) {
    int row = blockIdx.x;
    const float* xr = x + (size_t)row * DD;
    float ss = 0.f;
    for (int d = threadIdx.x; d < DD; d += 256) { float v = xr[d]; ss += v*v; }
    __shared__ float red[256];
    red[threadIdx.x] = ss; __syncthreads();
    for (int s = 128; s > 0; s >>= 1) {
        if (threadIdx.x < s) red[threadIdx.x] += red[threadIdx.x + s];
        __syncthreads();
    }
    float scale = rsqrtf(red[0] * (1.0f/DD) + 1e-5f);
    size_t base = (size_t)row * DD;
    for (int d = threadIdx.x; d < DD; d += 256) {
        u16 h, l;
        split2(xr[d] * scale * w[d], h, l);
        hh[base + d] = h; ll[base + d] = l;
    }
}

// ---------------- RoPE -------------------------------------------------------
__global__ void freq_kernel(float* __restrict__ freq) {
    int h = threadIdx.x;
    if (h < DD/2) {
        freq[h] = (float)exp2(-(double)h * (13.287712379549449 / 512.0));
    }
}

__global__ void rope_kernel(float* __restrict__ x, const float* __restrict__ freq) {
    int bs = blockIdx.x;
    int s  = bs & (SS - 1);
    size_t base = (size_t)bs * DD;
    for (int h = threadIdx.x; h < DD/2; h += 256) {
        float ang = (float)s * freq[h];
        float sn, cs;
        sincosf(ang, &sn, &cs);
        float x1 = x[base + h], x2 = x[base + 512 + h];
        x[base + h]       = x1*cs - x2*sn;
        x[base + 512 + h] = x1*sn + x2*cs;
    }
}

// ---------------- windowed causal attention (emits bf16 hi/lo) ---------------
__global__ __launch_bounds__(256)
void attn_kernel(const float* __restrict__ q, const float* __restrict__ k,
                 const float* __restrict__ v,
                 u16* __restrict__ oh, u16* __restrict__ ol) {
    int i = blockIdx.x, b = blockIdx.y;
    __shared__ float qs[DD];
    __shared__ float sc[WIN];
    __shared__ float red[256];
    const int tid = threadIdx.x, warp = tid >> 5, lane = tid & 31;

    const float* qr = q + ((size_t)b*SS + i) * DD;
    for (int d = tid; d < DD; d += 256) qs[d] = qr[d];
    __syncthreads();

    int j0 = max(0, i - WIN + 1);
    int nk = i - j0 + 1;

    for (int jj = warp; jj < nk; jj += 8) {
        const float* kr = k + ((size_t)b*SS + j0 + jj) * DD;
        float acc = 0.f;
        for (int c = lane; c < DD; c += 32) acc += qs[c] * kr[c];
        #pragma unroll
        for (int off = 16; off; off >>= 1) acc += __shfl_xor_sync(0xffffffffu, acc, off);
        if (lane == 0) sc[jj] = acc * (1.0f / 32.0f);
    }
    __syncthreads();

    float m = -INFINITY;
    for (int jj = tid; jj < nk; jj += 256) m = fmaxf(m, sc[jj]);
    red[tid] = m; __syncthreads();
    for (int s = 128; s > 0; s >>= 1) {
        if (tid < s) red[tid] = fmaxf(red[tid], red[tid + s]);
        __syncthreads();
    }
    float mx = red[0]; __syncthreads();
    float ssum = 0.f;
    for (int jj = tid; jj < nk; jj += 256) {
        float e = expf(sc[jj] - mx);
        sc[jj] = e; ssum += e;
    }
    red[tid] = ssum; __syncthreads();
    for (int s = 128; s > 0; s >>= 1) {
        if (tid < s) red[tid] += red[tid + s];
        __syncthreads();
    }
    float inv = 1.0f / red[0]; __syncthreads();
    for (int jj = tid; jj < nk; jj += 256) sc[jj] *= inv;
    __syncthreads();

    float a0 = 0.f, a1 = 0.f, a2 = 0.f, a3 = 0.f;
    for (int jj = 0; jj < nk; jj++) {
        float p = sc[jj];
        const float* vr = v + ((size_t)b*SS + j0 + jj) * DD;
        a0 += p * vr[tid];
        a1 += p * vr[tid + 256];
        a2 += p * vr[tid + 512];
        a3 += p * vr[tid + 768];
    }
    size_t base = ((size_t)b*SS + i) * DD;
    u16 h, l;
    split2(a0, h, l); oh[base + tid]       = h; ol[base + tid]       = l;
    split2(a1, h, l); oh[base + tid + 256] = h; ol[base + tid + 256] = l;
    split2(a2, h, l); oh[base + tid + 512] = h; ol[base + tid + 512] = l;
    split2(a3, h, l); oh[base + tid + 768] = h; ol[base + tid + 768] = l;
}

// ---------------- SwiGLU fused with bf16 hi/lo split -------------------------
__global__ void swiglu_split_kernel(const float* __restrict__ t1,
                                    const float* __restrict__ t3,
                                    u16* __restrict__ hh,
                                    u16* __restrict__ ll, int n) {
    int i = blockIdx.x * 256 + threadIdx.x;
    if (i < n) {
        float x = t1[i];
        float v = (x / (1.f + expf(-x))) * t3[i];
        u16 h, l;
        split2(v, h, l);
        hh[i] = h; ll[i] = l;
    }
}

// ---------------- segment max pooling ----------------------------------------
__device__ __forceinline__ unsigned enc_f(float f) {
    unsigned b = __float_as_uint(f);
    return (b & 0x80000000u) ? ~b : (b | 0x80000000u);
}
__device__ __forceinline__ float dec_f(unsigned u) {
    return __uint_as_float((u & 0x80000000u) ? (u & 0x7fffffffu) : ~u);
}

__global__ void pool_max_kernel(const float* __restrict__ x,
                                const int* __restrict__ patch,
                                unsigned* __restrict__ pool) {
    int bs = blockIdx.x;
    int b  = bs >> 11;
    int p  = patch[bs];
    unsigned* dst = pool + ((size_t)b*SS + p) * DD;
    const float* src = x + (size_t)bs * DD;
    for (int d = threadIdx.x; d < DD; d += 256)
        atomicMax(dst + d, enc_f(src[d]));
}

__global__ void gather_add_kernel(const float* __restrict__ embeds,
                                  const unsigned* __restrict__ pool,
                                  const int* __restrict__ patch,
                                  float* __restrict__ hd) {
    int bs = blockIdx.x;
    int b  = bs >> 11;
    int p  = patch[bs];
    const unsigned* src = pool + ((size_t)b*SS + p) * DD;
    size_t base = (size_t)bs * DD;
    for (int d = threadIdx.x; d < DD; d += 256) {
        float g = dec_f(src[d]);
        if (!isfinite(g)) g = 0.f;
        hd[base + d] = embeds[base + d] + g;
    }
}

// ---------------- GEMM driver -----------------------------------------------
static void gemm_tc(const u16* ah, const u16* al,
                    const u16* bh, const u16* bl,
                    float* C, int M, int N, int K, bool acc){
    dim3 grid(N / 128, M / 128);
    if (acc) mma_gemm_kernel<true ><<<grid, 256, GEMM_SMEM>>>(M, N, K, ah, al, bh, bl, C);
    else     mma_gemm_kernel<false><<<grid, 256, GEMM_SMEM>>>(M, N, K, ah, al, bh, bl, C);
}

// weight offsets in the split buffer (per-layer layout)
#define OFF_WQ 0ull
#define OFF_WK 1048576ull
#define OFF_WV 2097152ull
#define OFF_WO 3145728ull
#define OFF_W1 4194304ull
#define OFF_W2 7077888ull
#define OFF_W3 9961472ull
#define LAYER_STRIDE 12845056ull
#define OFF_OUTPROJ 25690112ull

static void run_layer(float* h, float* xn, float* q, float* k, float* v,
                      float* t1, float* t3, float* freq,
                      u16* wh, u16* wl, size_t base,
                      const float* n_attn, const float* n_ffn,
                      u16* ah, u16* al){
    rmsnorm_split_kernel<<<NROW, 256>>>(h, n_attn, ah, al);
    gemm_tc(ah, al, wh+base+OFF_WQ, wl+base+OFF_WQ, q, NROW, DD, DD, false);
    gemm_tc(ah, al, wh+base+OFF_WK, wl+base+OFF_WK, k, NROW, DD, DD, false);
    gemm_tc(ah, al, wh+base+OFF_WV, wl+base+OFF_WV, v, NROW, DD, DD, false);
    rope_kernel<<<NROW, 256>>>(q, freq);
    rope_kernel<<<NROW, 256>>>(k, freq);
    attn_kernel<<<dim3(SS, BB), 256>>>(q, k, v, ah, al);
    gemm_tc(ah, al, wh+base+OFF_WO, wl+base+OFF_WO, h, NROW, DD, DD, true);
    rmsnorm_split_kernel<<<NROW, 256>>>(h, n_ffn, ah, al);
    gemm_tc(ah, al, wh+base+OFF_W1, wl+base+OFF_W1, t1, NROW, DFFN, DD, false);
    gemm_tc(ah, al, wh+base+OFF_W3, wl+base+OFF_W3, t3, NROW, DFFN, DD, false);
    swiglu_split_kernel<<<(NROW*DFFN + 255)/256, 256>>>(t1, t3, ah, al, NROW*DFFN);
    gemm_tc(ah, al, wh+base+OFF_W2, wl+base+OFF_W2, h, NROW, DD, DFFN, true);
}

// ---------------- entry ------------------------------------------------------
extern "C" void kernel_launch(void* const* d_in, const int* in_sizes, int n_in,
                              void* d_out, int out_size) {
    const int*   ids      = (const int*)d_in[0];
    const float* tok_emb  = (const float*)d_in[1];
    const float* hash_emb = (const float*)d_in[2];
    const float* W[21];
    for (int i = 0; i < 21; i++) W[i] = (const float*)d_in[3 + i];
    float* out = (float*)d_out;

    float *embeds, *h, *xn, *q, *k, *v, *t1, *t3, *freq;
    unsigned* pool; int* patch;
    u16 *wh, *wl, *ah, *al;
    cudaGetSymbolAddress((void**)&embeds, g_embeds);
    cudaGetSymbolAddress((void**)&h,      g_h);
    cudaGetSymbolAddress((void**)&xn,     g_xn);
    cudaGetSymbolAddress((void**)&q,      g_q);
    cudaGetSymbolAddress((void**)&k,      g_k);
    cudaGetSymbolAddress((void**)&v,      g_v);
    cudaGetSymbolAddress((void**)&pool,   g_pool);
    cudaGetSymbolAddress((void**)&t1,     g_t1);
    cudaGetSymbolAddress((void**)&t3,     g_t3);
    cudaGetSymbolAddress((void**)&patch,  g_patch);
    cudaGetSymbolAddress((void**)&freq,   g_freq);
    cudaGetSymbolAddress((void**)&wh,     g_wh);
    cudaGetSymbolAddress((void**)&wl,     g_wl);
    cudaGetSymbolAddress((void**)&ah,     g_ah);
    cudaGetSymbolAddress((void**)&al,     g_al);

    cudaFuncSetAttribute(mma_gemm_kernel<false>,
                         cudaFuncAttributeMaxDynamicSharedMemorySize, GEMM_SMEM);
    cudaFuncSetAttribute(mma_gemm_kernel<true>,
                         cudaFuncAttributeMaxDynamicSharedMemorySize, GEMM_SMEM);

    // ---- split + transpose all weights into bf16 hi/lo ([N,K]) ----
    struct WI { int idx; int K; int N; size_t off; };
    const WI tab[15] = {
        { 0, DD,   DD,   OFF_WQ},               { 1, DD, DD, OFF_WK},
        { 2, DD,   DD,   OFF_WV},               { 3, DD, DD, OFF_WO},
        { 4, DD,   DFFN, OFF_W1},               { 5, DFFN, DD, OFF_W2},
        { 6, DD,   DFFN, OFF_W3},
        {10, DD,   DD,   LAYER_STRIDE+OFF_WQ},  {11, DD, DD, LAYER_STRIDE+OFF_WK},
        {12, DD,   DD,   LAYER_STRIDE+OFF_WV},  {13, DD, DD, LAYER_STRIDE+OFF_WO},
        {14, DD,   DFFN, LAYER_STRIDE+OFF_W1},  {15, DFFN, DD, LAYER_STRIDE+OFF_W2},
        {16, DD,   DFFN, LAYER_STRIDE+OFF_W3},
        {20, DD,   OUTV, OFF_OUTPROJ}
    };
    for (int i = 0; i < 15; i++){
        dim3 grid(tab[i].N / 32, tab[i].K / 32);
        wsplit_kernel<<<grid, dim3(32, 8)>>>(W[tab[i].idx], wh + tab[i].off,
                                             wl + tab[i].off, tab[i].K, tab[i].N);
    }

    freq_kernel<<<1, 512>>>(freq);
    hash_embed_kernel<<<NROW, 256>>>(ids, tok_emb, hash_emb, embeds, h);
    patch_kernel<<<1, 32>>>(ids, patch);

    // encoder layer
    run_layer(h, xn, q, k, v, t1, t3, freq, wh, wl, 0ull, W[7], W[8], ah, al);

    // encoder out-norm -> pooling -> decoder input
    rmsnorm_kernel<<<NROW, 256>>>(h, W[9], xn);
    cudaMemsetAsync(pool, 0, (size_t)NROW * DD * sizeof(unsigned));
    pool_max_kernel<<<NROW, 256>>>(xn, patch, pool);
    gather_add_kernel<<<NROW, 256>>>(embeds, pool, patch, h);

    // decoder layer
    run_layer(h, xn, q, k, v, t1, t3, freq, wh, wl, LAYER_STRIDE, W[17], W[18], ah, al);

    // final norm + output projection
    rmsnorm_split_kernel<<<NROW, 256>>>(h, W[19], ah, al);
    gemm_tc(ah, al, wh + OFF_OUTPROJ, wl + OFF_OUTPROJ, out, NROW, OUTV, DD, false);
}

// round 6
// speedup vs baseline: 2.4978x; 1.2289x over previous
#include <cuda_runtime.h>
#include <cuda_fp16.h>
#include <math.h>
#include <stdint.h>

#define BB 2
#define SS 2048
#define DD 1024
#define DFFN 2816
#define WIN 512
#define NROW (BB*SS)            // 4096
#define HV 32000
#define OUTV 32000
#define SPACE_TOK 36
#define BQ 16

typedef unsigned short u16;

// ---------------- scratch (device globals; no allocation allowed) ------------
__device__ float    g_embeds[NROW*DD];
__device__ float    g_h[NROW*DD];
__device__ float    g_xn[NROW*DD];
__device__ float    g_q[NROW*DD];
__device__ float    g_k[NROW*DD];
__device__ float    g_v[NROW*DD];
__device__ unsigned g_pool[NROW*DD];
__device__ float    g_t1[NROW*DFFN];
__device__ float    g_t3[NROW*DFFN];
__device__ int      g_patch[NROW];
__device__ float    g_freq[DD/2];
// fp16 weights (pre-transposed to [N,K]) and fp16 hi/lo activations
__device__ u16 g_wh[58458112];
__device__ u16 g_ah[(size_t)NROW*DFFN];
__device__ u16 g_al[(size_t)NROW*DFFN];

static __device__ __forceinline__ uint32_t smem_u32(const void* p){
    uint32_t a;
    asm("{ .reg .u64 t; cvta.to.shared.u64 t, %1; cvt.u32.u64 %0, t; }"
        : "=r"(a) : "l"(p));
    return a;
}
static __device__ __forceinline__ void split2(float v, u16& h, u16& l){
    __half hb = __float2half(v);
    h = __half_as_ushort(hb);
    l = __half_as_ushort(__float2half(v - __half2float(hb)));
}

// ================= mma.sync fp16x2 GEMM ======================================
// C[M,N] (+)= A[M,K] * W^T, W pre-transposed [N,K] single fp16.
// A = Ah + Al (fp16 each): C ~= Ah*B + Al*B; error ~2^-12 from W quantization.
// smem rows padded to 48B: (3r+c) mod 8 permutation => ldmatrix conflict-free.
#define TILE_B 6144          // 128 rows * 48 bytes
#define STAGE_B 18432        // Ah, Al, Bh tiles
#define GEMM_SMEM (2*STAGE_B)

static __device__ __forceinline__ void ldsm_x4(uint32_t* r, uint32_t addr){
    asm volatile("ldmatrix.sync.aligned.m8n8.x4.shared.b16 {%0,%1,%2,%3}, [%4];"
                 : "=r"(r[0]), "=r"(r[1]), "=r"(r[2]), "=r"(r[3]) : "r"(addr));
}
static __device__ __forceinline__ void ldsm_x2(uint32_t* r, uint32_t addr){
    asm volatile("ldmatrix.sync.aligned.m8n8.x2.shared.b16 {%0,%1}, [%2];"
                 : "=r"(r[0]), "=r"(r[1]) : "r"(addr));
}
static __device__ __forceinline__ void mma16816(float* d, const uint32_t* a, const uint32_t* b){
    asm volatile(
        "mma.sync.aligned.m16n8k16.row.col.f32.f16.f16.f32 "
        "{%0,%1,%2,%3}, {%4,%5,%6,%7}, {%8,%9}, {%0,%1,%2,%3};"
        : "+f"(d[0]), "+f"(d[1]), "+f"(d[2]), "+f"(d[3])
        : "r"(a[0]), "r"(a[1]), "r"(a[2]), "r"(a[3]), "r"(b[0]), "r"(b[1]));
}

template<bool ACC>
__global__ void __launch_bounds__(256)
mma_gemm_kernel(int M, int N, int K,
                const u16* __restrict__ Ah, const u16* __restrict__ Al,
                const u16* __restrict__ Bh,
                float* __restrict__ C)
{
    extern __shared__ char smem[];
    const uint32_t sb = smem_u32(smem);
    const int tid = threadIdx.x, lane = tid & 31, warp = tid >> 5;
    const int m0 = blockIdx.y * 128, n0 = blockIdx.x * 128;
    const int wm = (warp >> 2) * 64;     // warp M offset: 0/64
    const int wn = (warp & 3) * 32;      // warp N offset: 0/32/64/96

    const u16* srcp[3] = { Ah + (size_t)m0 * K, Al + (size_t)m0 * K,
                           Bh + (size_t)n0 * K };
    // 3 cp.async 16B chunks per thread (3 tiles x 128 rows x 2 chunks)
    int c_tile[3], c_row[3], c_ch[3];
    #pragma unroll
    for (int j = 0; j < 3; j++){
        int idx = tid + j*256;
        c_tile[j] = idx >> 8;
        c_row[j]  = (idx & 255) >> 1;
        c_ch[j]   = idx & 1;
    }

    float acc[4][4][4];
    #pragma unroll
    for (int a = 0; a < 4; a++)
        #pragma unroll
        for (int b = 0; b < 4; b++)
            #pragma unroll
            for (int c = 0; c < 4; c++) acc[a][b][c] = 0.f;

    const int nstage = K >> 4;

    // prologue
    #pragma unroll
    for (int j = 0; j < 3; j++){
        uint32_t dst = sb + c_tile[j]*TILE_B + c_row[j]*48 + c_ch[j]*16;
        const u16* src = srcp[c_tile[j]] + (size_t)c_row[j]*K + c_ch[j]*8;
        asm volatile("cp.async.cg.shared.global [%0], [%1], 16;" :: "r"(dst), "l"(src));
    }
    asm volatile("cp.async.commit_group;");

    const int arow = lane & 15, acolb = (lane >> 4) * 16;
    const int l2 = lane & 15;
    const int brow = l2 & 7, bcolb = ((l2 >> 3) & 1) * 16;

    for (int s = 0; s < nstage; s++){
        if (s + 1 < nstage){
            uint32_t sbase = sb + ((s + 1) & 1) * STAGE_B;
            int k0 = (s + 1) << 4;
            #pragma unroll
            for (int j = 0; j < 3; j++){
                uint32_t dst = sbase + c_tile[j]*TILE_B + c_row[j]*48 + c_ch[j]*16;
                const u16* src = srcp[c_tile[j]] + (size_t)c_row[j]*K + k0 + c_ch[j]*8;
                asm volatile("cp.async.cg.shared.global [%0], [%1], 16;" :: "r"(dst), "l"(src));
            }
        }
        asm volatile("cp.async.commit_group;");
        asm volatile("cp.async.wait_group 1;");
        __syncthreads();

        uint32_t base = sb + (s & 1) * STAGE_B;
        uint32_t aH[4][4], aL[4][4], bH[4][2];
        #pragma unroll
        for (int mi = 0; mi < 4; mi++){
            uint32_t ad = base + (wm + mi*16 + arow)*48 + acolb;
            ldsm_x4(aH[mi], ad);
            ldsm_x4(aL[mi], ad + TILE_B);
        }
        #pragma unroll
        for (int ni = 0; ni < 4; ni++){
            uint32_t bd = base + 2*TILE_B + (wn + ni*8 + brow)*48 + bcolb;
            ldsm_x2(bH[ni], bd);
        }
        #pragma unroll
        for (int mi = 0; mi < 4; mi++)
            #pragma unroll
            for (int ni = 0; ni < 4; ni++){
                mma16816(acc[mi][ni], aH[mi], bH[ni]);
                mma16816(acc[mi][ni], aL[mi], bH[ni]);
            }
        __syncthreads();
    }

    // epilogue
    #pragma unroll
    for (int mi = 0; mi < 4; mi++){
        int r0 = m0 + wm + mi*16 + (lane >> 2);
        #pragma unroll
        for (int ni = 0; ni < 4; ni++){
            int c0 = n0 + wn + ni*8 + (lane & 3)*2;
            float* p0 = C + (size_t)r0 * N + c0;
            float* p1 = p0 + (size_t)8 * N;
            float2 v0 = make_float2(acc[mi][ni][0], acc[mi][ni][1]);
            float2 v1 = make_float2(acc[mi][ni][2], acc[mi][ni][3]);
            if (ACC){
                float2 o0 = *(float2*)p0, o1 = *(float2*)p1;
                v0.x += o0.x; v0.y += o0.y; v1.x += o1.x; v1.y += o1.y;
            }
            *(float2*)p0 = v0;
            *(float2*)p1 = v1;
        }
    }
}

// ---- weight transpose + fp16 convert: W[K,N] -> Th[N,K] ---------------------
__global__ void wsplit_kernel(const float* __restrict__ W,
                              u16* __restrict__ Th, int K, int N){
    __shared__ float t[32][33];
    int k0 = blockIdx.y * 32, n0 = blockIdx.x * 32;
    int tx = threadIdx.x, ty = threadIdx.y;
    #pragma unroll
    for (int j = 0; j < 32; j += 8)
        t[ty + j][tx] = W[(size_t)(k0 + ty + j) * N + n0 + tx];
    __syncthreads();
    #pragma unroll
    for (int j = 0; j < 32; j += 8){
        float v = t[tx][ty + j];
        Th[(size_t)(n0 + ty + j) * K + k0 + tx] = __half_as_ushort(__float2half(v));
    }
}

// ---------------- hash n-gram embeddings ------------------------------------
__global__ void hash_embed_kernel(const int* __restrict__ ids,
                                  const float* __restrict__ tok_emb,
                                  const float* __restrict__ hash_emb,
                                  float* __restrict__ out,
                                  float* __restrict__ out2) {
    int bs = blockIdx.x;
    int s  = bs & (SS - 1);
    __shared__ const float* rows[4];
    if (threadIdx.x == 0) {
        unsigned g0 = (unsigned)ids[bs];
        unsigned g1 = (s >= 1) ? (unsigned)ids[bs-1] : 0u;
        unsigned g2 = (s >= 2) ? (unsigned)ids[bs-2] : 0u;
        unsigned g3 = (s >= 3) ? (unsigned)ids[bs-3] : 0u;
        rows[0] = tok_emb + (size_t)ids[bs] * DD;
        const unsigned mults[3] = {2654435761u, 805459861u, 2246822519u};
        for (int f = 0; f < 3; f++) {
            unsigned a = mults[f];
            unsigned h = g0;
            h = h*a + g1; h = h*a + g2; h = h*a + g3;
            rows[f+1] = hash_emb + ((size_t)f * HV + (h % HV)) * DD;
        }
    }
    __syncthreads();
    const float* r0 = rows[0]; const float* r1 = rows[1];
    const float* r2 = rows[2]; const float* r3 = rows[3];
    size_t base = (size_t)bs * DD;
    for (int d = threadIdx.x; d < DD; d += 256) {
        float v = r0[d] + r1[d] + r2[d] + r3[d];
        out[base + d]  = v;
        out2[base + d] = v;
    }
}

// ---------------- patch ids --------------------------------------------------
__global__ void patch_kernel(const int* __restrict__ ids, int* __restrict__ patch) {
    int b = threadIdx.x;
    if (b >= BB) return;
    int pid = -1;
    for (int s = 0; s < SS; s++) {
        bool start = (s == 0) || (ids[b*SS + s - 1] == SPACE_TOK);
        if (start) pid++;
        patch[b*SS + s] = pid;
    }
}

// ---------------- rmsnorm (fp32 out, pooling path) ---------------------------
__global__ void rmsnorm_kernel(const float* __restrict__ x,
                               const float* __restrict__ w,
                               float* __restrict__ y) {
    int row = blockIdx.x;
    const float* xr = x + (size_t)row * DD;
    float ss = 0.f;
    for (int d = threadIdx.x; d < DD; d += 256) { float v = xr[d]; ss += v*v; }
    __shared__ float red[256];
    red[threadIdx.x] = ss; __syncthreads();
    for (int s = 128; s > 0; s >>= 1) {
        if (threadIdx.x < s) red[threadIdx.x] += red[threadIdx.x + s];
        __syncthreads();
    }
    float scale = rsqrtf(red[0] * (1.0f/DD) + 1e-5f);
    float* yr = y + (size_t)row * DD;
    for (int d = threadIdx.x; d < DD; d += 256) yr[d] = xr[d] * scale * w[d];
}

// ---------------- rmsnorm fused with fp16 hi/lo split ------------------------
__global__ void rmsnorm_split_kernel(const float* __restrict__ x,
                                     const float* __restrict__ w,
                                     u16* __restrict__ hh,
                                     u16* __restrict__ ll) {
    int row = blockIdx.x;
    const float* xr = x + (size_t)row * DD;
    float ss = 0.f;
    for (int d = threadIdx.x; d < DD; d += 256) { float v = xr[d]; ss += v*v; }
    __shared__ float red[256];
    red[threadIdx.x] = ss; __syncthreads();
    for (int s = 128; s > 0; s >>= 1) {
        if (threadIdx.x < s) red[threadIdx.x] += red[threadIdx.x + s];
        __syncthreads();
    }
    float scale = rsqrtf(red[0] * (1.0f/DD) + 1e-5f);
    size_t base = (size_t)row * DD;
    for (int d = threadIdx.x; d < DD; d += 256) {
        u16 h, l;
        split2(xr[d] * scale * w[d], h, l);
        hh[base + d] = h; ll[base + d] = l;
    }
}

// ---------------- RoPE -------------------------------------------------------
__global__ void freq_kernel(float* __restrict__ freq) {
    int h = threadIdx.x;
    if (h < DD/2) {
        freq[h] = (float)exp2(-(double)h * (13.287712379549449 / 512.0));
    }
}

__global__ void rope_kernel(float* __restrict__ x, const float* __restrict__ freq) {
    int bs = blockIdx.x;
    int s  = bs & (SS - 1);
    size_t base = (size_t)bs * DD;
    for (int h = threadIdx.x; h < DD/2; h += 256) {
        float ang = (float)s * freq[h];
        float sn, cs;
        sincosf(ang, &sn, &cs);
        float x1 = x[base + h], x2 = x[base + 512 + h];
        x[base + h]       = x1*cs - x2*sn;
        x[base + 512 + h] = x1*sn + x2*cs;
    }
}

// ---------------- tiled windowed causal attention ---------------------------
// 16 queries per CTA; 8 warps x 2 queries each. K/V rows shared via L1.
// Scores live in warp-private smem rows -> no block-level syncs needed.
__global__ __launch_bounds__(256)
void attn_tile_kernel(const float* __restrict__ q, const float* __restrict__ k,
                      const float* __restrict__ v,
                      u16* __restrict__ oh, u16* __restrict__ ol) {
    __shared__ float sc[BQ][544];
    const int i0 = blockIdx.x * BQ, b = blockIdx.y;
    const int tid = threadIdx.x, warp = tid >> 5, lane = tid & 31;
    const int j_lo = max(0, i0 - WIN + 1);
    const int nk = i0 + BQ - j_lo;      // keys covering all queries in tile

    const int qa = 2*warp, qb = 2*warp + 1;
    const int ia = i0 + qa, ib = i0 + qb;

    // cache both query rows in registers (fp32)
    float4 qra[8], qrb[8];
    const float4* qpa = (const float4*)(q + ((size_t)b*SS + ia)*DD);
    const float4* qpb = (const float4*)(q + ((size_t)b*SS + ib)*DD);
    #pragma unroll
    for (int it = 0; it < 8; it++){
        qra[it] = qpa[lane + it*32];
        qrb[it] = qpb[lane + it*32];
    }

    // scores
    for (int jj = 0; jj < nk; jj++){
        int jg = j_lo + jj;
        const float4* kr = (const float4*)(k + ((size_t)b*SS + jg)*DD);
        float da = 0.f, db = 0.f;
        #pragma unroll
        for (int it = 0; it < 8; it++){
            float4 kv = kr[lane + it*32];
            da += qra[it].x*kv.x + qra[it].y*kv.y + qra[it].z*kv.z + qra[it].w*kv.w;
            db += qrb[it].x*kv.x + qrb[it].y*kv.y + qrb[it].z*kv.z + qrb[it].w*kv.w;
        }
        #pragma unroll
        for (int off = 16; off; off >>= 1){
            da += __shfl_xor_sync(0xffffffffu, da, off);
            db += __shfl_xor_sync(0xffffffffu, db, off);
        }
        if (lane == 0){
            bool va = (jg <= ia) && (ia - jg < WIN);
            bool vb = (jg <= ib) && (ib - jg < WIN);
            sc[qa][jj] = va ? da * 0.03125f : -1e30f;
            sc[qb][jj] = vb ? db * 0.03125f : -1e30f;
        }
    }
    __syncwarp();

    // softmax (warp-private rows)
    #pragma unroll
    for (int qi = 0; qi < 2; qi++){
        float* row = sc[2*warp + qi];
        float m = -1e30f;
        for (int jj = lane; jj < nk; jj += 32) m = fmaxf(m, row[jj]);
        #pragma unroll
        for (int off = 16; off; off >>= 1) m = fmaxf(m, __shfl_xor_sync(0xffffffffu, m, off));
        float s = 0.f;
        for (int jj = lane; jj < nk; jj += 32){
            float e = __expf(row[jj] - m);
            row[jj] = e; s += e;
        }
        #pragma unroll
        for (int off = 16; off; off >>= 1) s += __shfl_xor_sync(0xffffffffu, s, off);
        float inv = 1.f / s;
        for (int jj = lane; jj < nk; jj += 32) row[jj] *= inv;
    }
    __syncwarp();

    // PV
    float4 aca[8], acb[8];
    #pragma unroll
    for (int it = 0; it < 8; it++){
        aca[it] = make_float4(0.f,0.f,0.f,0.f);
        acb[it] = make_float4(0.f,0.f,0.f,0.f);
    }
    for (int jj = 0; jj < nk; jj++){
        float pa = sc[qa][jj], pb = sc[qb][jj];
        if (pa == 0.f && pb == 0.f) continue;           // warp-uniform
        const float4* vr = (const float4*)(v + ((size_t)b*SS + j_lo + jj)*DD);
        #pragma unroll
        for (int it = 0; it < 8; it++){
            float4 vv = vr[lane + it*32];
            aca[it].x += pa*vv.x; aca[it].y += pa*vv.y;
            aca[it].z += pa*vv.z; aca[it].w += pa*vv.w;
            acb[it].x += pb*vv.x; acb[it].y += pb*vv.y;
            acb[it].z += pb*vv.z; acb[it].w += pb*vv.w;
        }
    }

    // emit fp16 hi/lo
    size_t ba = ((size_t)b*SS + ia)*DD, bb = ((size_t)b*SS + ib)*DD;
    #pragma unroll
    for (int it = 0; it < 8; it++){
        int off = lane*4 + it*128;
        ushort4 H, L;
        split2(aca[it].x, H.x, L.x); split2(aca[it].y, H.y, L.y);
        split2(aca[it].z, H.z, L.z); split2(aca[it].w, H.w, L.w);
        *(ushort4*)(oh + ba + off) = H; *(ushort4*)(ol + ba + off) = L;
        split2(acb[it].x, H.x, L.x); split2(acb[it].y, H.y, L.y);
        split2(acb[it].z, H.z, L.z); split2(acb[it].w, H.w, L.w);
        *(ushort4*)(oh + bb + off) = H; *(ushort4*)(ol + bb + off) = L;
    }
}

// ---------------- SwiGLU fused with fp16 hi/lo split -------------------------
__global__ void swiglu_split_kernel(const float* __restrict__ t1,
                                    const float* __restrict__ t3,
                                    u16* __restrict__ hh,
                                    u16* __restrict__ ll, int n) {
    int i = blockIdx.x * 256 + threadIdx.x;
    if (i < n) {
        float x = t1[i];
        float v = (x / (1.f + expf(-x))) * t3[i];
        u16 h, l;
        split2(v, h, l);
        hh[i] = h; ll[i] = l;
    }
}

// ---------------- segment max pooling ----------------------------------------
__device__ __forceinline__ unsigned enc_f(float f) {
    unsigned b = __float_as_uint(f);
    return (b & 0x80000000u) ? ~b : (b | 0x80000000u);
}
__device__ __forceinline__ float dec_f(unsigned u) {
    return __uint_as_float((u & 0x80000000u) ? (u & 0x7fffffffu) : ~u);
}

__global__ void pool_max_kernel(const float* __restrict__ x,
                                const int* __restrict__ patch,
                                unsigned* __restrict__ pool) {
    int bs = blockIdx.x;
    int b  = bs >> 11;
    int p  = patch[bs];
    unsigned* dst = pool + ((size_t)b*SS + p) * DD;
    const float* src = x + (size_t)bs * DD;
    for (int d = threadIdx.x; d < DD; d += 256)
        atomicMax(dst + d, enc_f(src[d]));
}

__global__ void gather_add_kernel(const float* __restrict__ embeds,
                                  const unsigned* __restrict__ pool,
                                  const int* __restrict__ patch,
                                  float* __restrict__ hd) {
    int bs = blockIdx.x;
    int b  = bs >> 11;
    int p  = patch[bs];
    const unsigned* src = pool + ((size_t)b*SS + p) * DD;
    size_t base = (size_t)bs * DD;
    for (int d = threadIdx.x; d < DD; d += 256) {
        float g = dec_f(src[d]);
        if (!isfinite(g)) g = 0.f;
        hd[base + d] = embeds[base + d] + g;
    }
}

// ---------------- GEMM driver -----------------------------------------------
static void gemm_tc(const u16* ah, const u16* al, const u16* bh,
                    float* C, int M, int N, int K, bool acc){
    dim3 grid(N / 128, M / 128);
    if (acc) mma_gemm_kernel<true ><<<grid, 256, GEMM_SMEM>>>(M, N, K, ah, al, bh, C);
    else     mma_gemm_kernel<false><<<grid, 256, GEMM_SMEM>>>(M, N, K, ah, al, bh, C);
}

// weight offsets (element counts, per-layer layout)
#define OFF_WQ 0ull
#define OFF_WK 1048576ull
#define OFF_WV 2097152ull
#define OFF_WO 3145728ull
#define OFF_W1 4194304ull
#define OFF_W2 7077888ull
#define OFF_W3 9961472ull
#define LAYER_STRIDE 12845056ull
#define OFF_OUTPROJ 25690112ull

static void run_layer(float* h, float* q, float* k, float* v,
                      float* t1, float* t3, float* freq,
                      u16* wh, size_t base,
                      const float* n_attn, const float* n_ffn,
                      u16* ah, u16* al){
    rmsnorm_split_kernel<<<NROW, 256>>>(h, n_attn, ah, al);
    gemm_tc(ah, al, wh+base+OFF_WQ, q, NROW, DD, DD, false);
    gemm_tc(ah, al, wh+base+OFF_WK, k, NROW, DD, DD, false);
    gemm_tc(ah, al, wh+base+OFF_WV, v, NROW, DD, DD, false);
    rope_kernel<<<NROW, 256>>>(q, freq);
    rope_kernel<<<NROW, 256>>>(k, freq);
    attn_tile_kernel<<<dim3(SS/BQ, BB), 256>>>(q, k, v, ah, al);
    gemm_tc(ah, al, wh+base+OFF_WO, h, NROW, DD, DD, true);
    rmsnorm_split_kernel<<<NROW, 256>>>(h, n_ffn, ah, al);
    gemm_tc(ah, al, wh+base+OFF_W1, t1, NROW, DFFN, DD, false);
    gemm_tc(ah, al, wh+base+OFF_W3, t3, NROW, DFFN, DD, false);
    swiglu_split_kernel<<<(NROW*DFFN + 255)/256, 256>>>(t1, t3, ah, al, NROW*DFFN);
    gemm_tc(ah, al, wh+base+OFF_W2, h, NROW, DD, DFFN, true);
}

// ---------------- entry ------------------------------------------------------
extern "C" void kernel_launch(void* const* d_in, const int* in_sizes, int n_in,
                              void* d_out, int out_size) {
    const int*   ids      = (const int*)d_in[0];
    const float* tok_emb  = (const float*)d_in[1];
    const float* hash_emb = (const float*)d_in[2];
    const float* W[21];
    for (int i = 0; i < 21; i++) W[i] = (const float*)d_in[3 + i];
    float* out = (float*)d_out;

    float *embeds, *h, *xn, *q, *k, *v, *t1, *t3, *freq;
    unsigned* pool; int* patch;
    u16 *wh, *ah, *al;
    cudaGetSymbolAddress((void**)&embeds, g_embeds);
    cudaGetSymbolAddress((void**)&h,      g_h);
    cudaGetSymbolAddress((void**)&xn,     g_xn);
    cudaGetSymbolAddress((void**)&q,      g_q);
    cudaGetSymbolAddress((void**)&k,      g_k);
    cudaGetSymbolAddress((void**)&v,      g_v);
    cudaGetSymbolAddress((void**)&pool,   g_pool);
    cudaGetSymbolAddress((void**)&t1,     g_t1);
    cudaGetSymbolAddress((void**)&t3,     g_t3);
    cudaGetSymbolAddress((void**)&patch,  g_patch);
    cudaGetSymbolAddress((void**)&freq,   g_freq);
    cudaGetSymbolAddress((void**)&wh,     g_wh);
    cudaGetSymbolAddress((void**)&ah,     g_ah);
    cudaGetSymbolAddress((void**)&al,     g_al);

    cudaFuncSetAttribute(mma_gemm_kernel<false>,
                         cudaFuncAttributeMaxDynamicSharedMemorySize, GEMM_SMEM);
    cudaFuncSetAttribute(mma_gemm_kernel<true>,
                         cudaFuncAttributeMaxDynamicSharedMemorySize, GEMM_SMEM);

    // ---- transpose + fp16-convert all weights ([N,K]) ----
    struct WI { int idx; int K; int N; size_t off; };
    const WI tab[15] = {
        { 0, DD,   DD,   OFF_WQ},               { 1, DD, DD, OFF_WK},
        { 2, DD,   DD,   OFF_WV},               { 3, DD, DD, OFF_WO},
        { 4, DD,   DFFN, OFF_W1},               { 5, DFFN, DD, OFF_W2},
        { 6, DD,   DFFN, OFF_W3},
        {10, DD,   DD,   LAYER_STRIDE+OFF_WQ},  {11, DD, DD, LAYER_STRIDE+OFF_WK},
        {12, DD,   DD,   LAYER_STRIDE+OFF_WV},  {13, DD, DD, LAYER_STRIDE+OFF_WO},
        {14, DD,   DFFN, LAYER_STRIDE+OFF_W1},  {15, DFFN, DD, LAYER_STRIDE+OFF_W2},
        {16, DD,   DFFN, LAYER_STRIDE+OFF_W3},
        {20, DD,   OUTV, OFF_OUTPROJ}
    };
    for (int i = 0; i < 15; i++){
        dim3 grid(tab[i].N / 32, tab[i].K / 32);
        wsplit_kernel<<<grid, dim3(32, 8)>>>(W[tab[i].idx], wh + tab[i].off,
                                             tab[i].K, tab[i].N);
    }

    freq_kernel<<<1, 512>>>(freq);
    hash_embed_kernel<<<NROW, 256>>>(ids, tok_emb, hash_emb, embeds, h);
    patch_kernel<<<1, 32>>>(ids, patch);

    // encoder layer
    run_layer(h, q, k, v, t1, t3, freq, wh, 0ull, W[7], W[8], ah, al);

    // encoder out-norm -> pooling -> decoder input
    rmsnorm_kernel<<<NROW, 256>>>(h, W[9], xn);
    cudaMemsetAsync(pool, 0, (size_t)NROW * DD * sizeof(unsigned));
    pool_max_kernel<<<NROW, 256>>>(xn, patch, pool);
    gather_add_kernel<<<NROW, 256>>>(embeds, pool, patch, h);

    // decoder layer
    run_layer(h, q, k, v, t1, t3, freq, wh, LAYER_STRIDE, W[17], W[18], ah, al);

    // final norm + output projection
    rmsnorm_split_kernel<<<NROW, 256>>>(h, W[19], ah, al);
    gemm_tc(ah, al, wh + OFF_OUTPROJ, out, NROW, OUTV, DD, false);
}